// round 9
// baseline (speedup 1.0000x reference)
#include <cuda_runtime.h>
#include <cuda_bf16.h>
#include <cstdint>

#define N_NODES 100000
#define N_EDGES 6400000
#define N_MASK_WORDS (N_NODES / 32)   // 3125
#define LOG2_10 3.3219280948873623f

// Scratch (allocation-free rule: __device__ globals).
__device__ float        d_syn[N_NODES];
__device__ unsigned int d_mask[N_MASK_WORDS];   // bit v = is_input[v]

// ---------------------------------------------------------------------------
// Phase 0 (prep): zero d_syn (float4) AND build the 12.5KB is_input bitmask.
// 25000 threads; first 3125 also build one mask word each (32 contiguous
// int32 loads = 128B per thread, coalesced across the warp).
// ---------------------------------------------------------------------------
__global__ void __launch_bounds__(256) prep_kernel(const int* __restrict__ is_input)
{
    const int i = blockIdx.x * blockDim.x + threadIdx.x;
    if (i < N_NODES / 4) {
        reinterpret_cast<float4*>(d_syn)[i] = make_float4(0.f, 0.f, 0.f, 0.f);
    }
    if (i < N_MASK_WORDS) {
        const int4* p = reinterpret_cast<const int4*>(is_input + 32 * i);
        unsigned int m = 0;
#pragma unroll
        for (int k = 0; k < 8; k++) {
            int4 v = __ldg(p + k);
            m |= (v.x != 0 ? 1u : 0u) << (4 * k + 0);
            m |= (v.y != 0 ? 1u : 0u) << (4 * k + 1);
            m |= (v.z != 0 ? 1u : 0u) << (4 * k + 2);
            m |= (v.w != 0 ? 1u : 0u) << (4 * k + 3);
        }
        d_mask[i] = m;
    }
}

// ---------------------------------------------------------------------------
// Phase 1: edge scatter, 4 edges/thread (vectorized int4/float4 loads).
// Predicate on the L1-resident bitmask: syn for input nodes is discarded by
// the where(), so skip both the rates gather and the atomic (halves L2
// atomic sector traffic, removes the 205MB is_input gather entirely).
// ---------------------------------------------------------------------------
__device__ __forceinline__ bool not_input(int v) {
    return ((__ldg(d_mask + (v >> 5)) >> (v & 31)) & 1u) == 0u;
}

__global__ void __launch_bounds__(256) edge_kernel(
    const float* __restrict__ rates,
    const float* __restrict__ weights,
    const int*   __restrict__ src,
    const int*   __restrict__ dst)
{
    const int e4 = blockIdx.x * blockDim.x + threadIdx.x;   // 0 .. E/4-1
    if (e4 >= N_EDGES / 4) return;

    const int4   s = __ldg(reinterpret_cast<const int4*>(src) + e4);
    const int4   d = __ldg(reinterpret_cast<const int4*>(dst) + e4);
    const float4 w = __ldg(reinterpret_cast<const float4*>(weights) + e4);

    if (not_input(d.x)) atomicAdd(&d_syn[d.x], __ldg(rates + s.x) * w.x);
    if (not_input(d.y)) atomicAdd(&d_syn[d.y], __ldg(rates + s.y) * w.y);
    if (not_input(d.z)) atomicAdd(&d_syn[d.z], __ldg(rates + s.z) * w.z);
    if (not_input(d.w)) atomicAdd(&d_syn[d.w], __ldg(rates + s.w) * w.w);
}

// ---------------------------------------------------------------------------
// Phase 2: per-node epilogue.
// total = (is_input ? ext : syn) + baseline
// out   = (-r + 10^gain * tanh(total)) / tau
// ---------------------------------------------------------------------------
__global__ void __launch_bounds__(256) node_kernel(
    const float* __restrict__ rates,
    const float* __restrict__ gain,
    const float* __restrict__ tau,
    const float* __restrict__ baseline,
    const float* __restrict__ ext_input,
    const int*   __restrict__ is_input,
    float* __restrict__ out)
{
    int i = blockIdx.x * blockDim.x + threadIdx.x;
    if (i >= N_NODES) return;

    const float syn   = d_syn[i];
    const float ext   = __ldg(ext_input + i);
    const float total = (__ldg(is_input + i) ? ext : syn) + __ldg(baseline + i);
    const float act   = tanhf(total);
    const float g     = exp2f(__ldg(gain + i) * LOG2_10);   // 10^gain
    out[i] = (-__ldg(rates + i) + g * act) / __ldg(tau + i);
}

// ---------------------------------------------------------------------------
// Launch. Input order (metadata): rates, weights, gain, time_constant,
// baseline, ext_input, src, dst, is_input. Output: float32[N_NODES].
// ---------------------------------------------------------------------------
extern "C" void kernel_launch(void* const* d_in, const int* in_sizes, int n_in,
                              void* d_out, int out_size)
{
    const float* rates    = (const float*)d_in[0];
    const float* weights  = (const float*)d_in[1];
    const float* gain     = (const float*)d_in[2];
    const float* tau      = (const float*)d_in[3];
    const float* baseline = (const float*)d_in[4];
    const float* ext      = (const float*)d_in[5];
    const int*   src      = (const int*)d_in[6];
    const int*   dst      = (const int*)d_in[7];
    const int*   is_input = (const int*)d_in[8];
    float* out = (float*)d_out;

    const int prep_blocks = (N_NODES / 4 + 255) / 256;      // covers mask words too
    const int node_blocks = (N_NODES + 255) / 256;
    const int edge_blocks = (N_EDGES / 4 + 255) / 256;

    prep_kernel<<<prep_blocks, 256>>>(is_input);
    edge_kernel<<<edge_blocks, 256>>>(rates, weights, src, dst);
    node_kernel<<<node_blocks, 256>>>(rates, gain, tau, baseline, ext, is_input, out);
}

// round 14
// speedup vs baseline: 1.3729x; 1.3729x over previous
#include <cuda_runtime.h>
#include <cuda_bf16.h>
#include <cstdint>

#define N_NODES 100000
#define N_EDGES 6400000
#define N_MASK_WORDS (N_NODES / 32)   // 3125
#define LOG2_10 3.3219280948873623f

// Scratch (allocation-free rule: __device__ globals).
__device__ float        d_syn[N_NODES];
__device__ unsigned int d_mask[N_MASK_WORDS];   // bit v = is_input[v]

// ---------------------------------------------------------------------------
// Phase 0 (prep): zero d_syn (float4) AND build the 12.5KB is_input bitmask.
// 25000 threads; first 3125 also build one mask word each (32 contiguous
// int32 loads = 128B per thread, coalesced across the warp).
// ---------------------------------------------------------------------------
__global__ void __launch_bounds__(256) prep_kernel(const int* __restrict__ is_input)
{
    const int i = blockIdx.x * blockDim.x + threadIdx.x;
    if (i < N_NODES / 4) {
        reinterpret_cast<float4*>(d_syn)[i] = make_float4(0.f, 0.f, 0.f, 0.f);
    }
    if (i < N_MASK_WORDS) {
        const int4* p = reinterpret_cast<const int4*>(is_input + 32 * i);
        unsigned int m = 0;
#pragma unroll
        for (int k = 0; k < 8; k++) {
            int4 v = __ldg(p + k);
            m |= (v.x != 0 ? 1u : 0u) << (4 * k + 0);
            m |= (v.y != 0 ? 1u : 0u) << (4 * k + 1);
            m |= (v.z != 0 ? 1u : 0u) << (4 * k + 2);
            m |= (v.w != 0 ? 1u : 0u) << (4 * k + 3);
        }
        d_mask[i] = m;
    }
}

// ---------------------------------------------------------------------------
// Phase 1: edge scatter, 4 edges/thread (vectorized int4/float4 loads).
// Predicate on the L1-resident bitmask: syn for input nodes is discarded by
// the where(), so skip both the rates gather and the atomic (halves L2
// atomic sector traffic, removes the 205MB is_input gather entirely).
// ---------------------------------------------------------------------------
__device__ __forceinline__ bool not_input(int v) {
    return ((__ldg(d_mask + (v >> 5)) >> (v & 31)) & 1u) == 0u;
}

__global__ void __launch_bounds__(256) edge_kernel(
    const float* __restrict__ rates,
    const float* __restrict__ weights,
    const int*   __restrict__ src,
    const int*   __restrict__ dst)
{
    const int e4 = blockIdx.x * blockDim.x + threadIdx.x;   // 0 .. E/4-1
    if (e4 >= N_EDGES / 4) return;

    const int4   s = __ldg(reinterpret_cast<const int4*>(src) + e4);
    const int4   d = __ldg(reinterpret_cast<const int4*>(dst) + e4);
    const float4 w = __ldg(reinterpret_cast<const float4*>(weights) + e4);

    if (not_input(d.x)) atomicAdd(&d_syn[d.x], __ldg(rates + s.x) * w.x);
    if (not_input(d.y)) atomicAdd(&d_syn[d.y], __ldg(rates + s.y) * w.y);
    if (not_input(d.z)) atomicAdd(&d_syn[d.z], __ldg(rates + s.z) * w.z);
    if (not_input(d.w)) atomicAdd(&d_syn[d.w], __ldg(rates + s.w) * w.w);
}

// ---------------------------------------------------------------------------
// Phase 2: per-node epilogue.
// total = (is_input ? ext : syn) + baseline
// out   = (-r + 10^gain * tanh(total)) / tau
// ---------------------------------------------------------------------------
__global__ void __launch_bounds__(256) node_kernel(
    const float* __restrict__ rates,
    const float* __restrict__ gain,
    const float* __restrict__ tau,
    const float* __restrict__ baseline,
    const float* __restrict__ ext_input,
    const int*   __restrict__ is_input,
    float* __restrict__ out)
{
    int i = blockIdx.x * blockDim.x + threadIdx.x;
    if (i >= N_NODES) return;

    const float syn   = d_syn[i];
    const float ext   = __ldg(ext_input + i);
    const float total = (__ldg(is_input + i) ? ext : syn) + __ldg(baseline + i);
    const float act   = tanhf(total);
    const float g     = exp2f(__ldg(gain + i) * LOG2_10);   // 10^gain
    out[i] = (-__ldg(rates + i) + g * act) / __ldg(tau + i);
}

// ---------------------------------------------------------------------------
// Launch. Input order (metadata): rates, weights, gain, time_constant,
// baseline, ext_input, src, dst, is_input. Output: float32[N_NODES].
// ---------------------------------------------------------------------------
extern "C" void kernel_launch(void* const* d_in, const int* in_sizes, int n_in,
                              void* d_out, int out_size)
{
    const float* rates    = (const float*)d_in[0];
    const float* weights  = (const float*)d_in[1];
    const float* gain     = (const float*)d_in[2];
    const float* tau      = (const float*)d_in[3];
    const float* baseline = (const float*)d_in[4];
    const float* ext      = (const float*)d_in[5];
    const int*   src      = (const int*)d_in[6];
    const int*   dst      = (const int*)d_in[7];
    const int*   is_input = (const int*)d_in[8];
    float* out = (float*)d_out;

    const int prep_blocks = (N_NODES / 4 + 255) / 256;      // covers mask words too
    const int node_blocks = (N_NODES + 255) / 256;
    const int edge_blocks = (N_EDGES / 4 + 255) / 256;

    prep_kernel<<<prep_blocks, 256>>>(is_input);
    edge_kernel<<<edge_blocks, 256>>>(rates, weights, src, dst);
    node_kernel<<<node_blocks, 256>>>(rates, gain, tau, baseline, ext, is_input, out);
}